// round 10
// baseline (speedup 1.0000x reference)
#include <cuda_runtime.h>
#include <cuda_bf16.h>
#include <cuda_fp16.h>
#include <cstdint>

#define Bb 8
#define Ll 4096
#define Hh 512
#define Cc 64
#define Aa 512
#define BL (Bb*Ll)
#define NEGV (-1000000000.0f)
#define OUT_ATT ((size_t)BL*Hh)

// ---- GEMM1 config: GM=64, A resident, 2 CTAs/SM ----
#define GM 64
#define ABYTES (GM*1024)
#define BROW 80
#define BSZ (128*BROW)
#define SM_B ABYTES
#define GEMM_SMEM (ABYTES + 2*BSZ)

// ---------------- scratch ----------------
__device__ float g_logits[BL];
__device__ float g_ctx[(size_t)Bb*Cc*Hh];
__device__ int   g_hasany[Bb*Cc];
__device__ int   g_maxi[Bb];
__device__ __nv_bfloat16 g_wbf_t[(size_t)Aa*Hh];

// ---------------- helpers ----------------
__device__ __forceinline__ uint32_t smem_u32(const void* p) {
    uint32_t a;
    asm("{ .reg .u64 t; cvta.to.shared.u64 t, %1; cvt.u32.u64 %0, t; }" : "=r"(a) : "l"(p));
    return a;
}
__device__ __forceinline__ void cpasync16(uint32_t dst, const void* src) {
    asm volatile("cp.async.cg.shared.global [%0], [%1], 16;" :: "r"(dst), "l"(src));
}
__device__ __forceinline__ void cp_commit() { asm volatile("cp.async.commit_group;"); }
template<int N> __device__ __forceinline__ void cp_wait() {
    asm volatile("cp.async.wait_group %0;" :: "n"(N));
}
__device__ __forceinline__ void ldsm_x4(uint32_t* r, uint32_t addr) {
    asm volatile("ldmatrix.sync.aligned.m8n8.x4.shared.b16 {%0,%1,%2,%3}, [%4];"
        : "=r"(r[0]), "=r"(r[1]), "=r"(r[2]), "=r"(r[3]) : "r"(addr));
}
__device__ __forceinline__ void mma16816(float* c, const uint32_t* a, const uint32_t* b) {
    asm volatile(
        "mma.sync.aligned.m16n8k16.row.col.f32.bf16.bf16.f32 "
        "{%0,%1,%2,%3}, {%4,%5,%6,%7}, {%8,%9}, {%0,%1,%2,%3};"
        : "+f"(c[0]), "+f"(c[1]), "+f"(c[2]), "+f"(c[3])
        : "r"(a[0]), "r"(a[1]), "r"(a[2]), "r"(a[3]), "r"(b[0]), "r"(b[1]));
}
__device__ __forceinline__ void mma_tf32(float* c, const uint32_t* a, const uint32_t* b) {
    asm volatile(
        "mma.sync.aligned.m16n8k8.row.col.f32.tf32.tf32.f32 "
        "{%0,%1,%2,%3}, {%4,%5,%6,%7}, {%8,%9}, {%0,%1,%2,%3};"
        : "+f"(c[0]), "+f"(c[1]), "+f"(c[2]), "+f"(c[3])
        : "r"(a[0]), "r"(a[1]), "r"(a[2]), "r"(a[3]), "r"(b[0]), "r"(b[1]));
}
__device__ __forceinline__ uint32_t f2tf32(float x) {
    uint32_t r;
    asm("cvt.rna.tf32.f32 %0, %1;" : "=r"(r) : "f"(x));
    return r;
}
__device__ __forceinline__ uint32_t tanh2(uint32_t x) {
    uint32_t r;
    asm("tanh.approx.f16x2 %0, %1;" : "=r"(r) : "r"(x));
    return r;
}

// ---------------- transpose + convert W ----------------
__global__ void k_cvt_wT(const float* __restrict__ W) {
    __shared__ float tile[32][33];
    int tx = threadIdx.x, ty = threadIdx.y;
    int k = blockIdx.x * 32 + ty;
    int n = blockIdx.y * 32 + tx;
    tile[ty][tx] = W[(size_t)k * Aa + n];
    __syncthreads();
    int no = blockIdx.y * 32 + ty;
    int ko = blockIdx.x * 32 + tx;
    g_wbf_t[(size_t)no * Hh + ko] = __float2bfloat16(tile[tx][ty]);
}

// ---------------- per-batch max count ----------------
__global__ void k_maxcount(const int* __restrict__ cnt) {
    int b = blockIdx.x >> 3, seg = blockIdx.x & 7;
    int v = cnt[b*Ll + seg*512 + threadIdx.x];
    #pragma unroll
    for (int o = 16; o; o >>= 1) v = max(v, __shfl_xor_sync(0xffffffffu, v, o));
    if ((threadIdx.x & 31) == 0) atomicMax(&g_maxi[b], v);
}

// ---------------- GEMM1 v4 (unchanged) ----------------
extern __shared__ char smem_raw[];

__global__ __launch_bounds__(256)
void k_gemm1_v4(const float* __restrict__ Hd,
                const float* __restrict__ pb, const float* __restrict__ sw,
                const int* __restrict__ cnt, const float* __restrict__ sb) {
    uint32_t smem_base = smem_u32(smem_raw);
    int tid = threadIdx.x, lane = tid & 31, wid = tid >> 5;
    int wm = wid >> 2, wn = wid & 3;
    int m0 = blockIdx.x * GM;

    #pragma unroll
    for (int u = 0; u < 2; u++) {
        int e = u * 256 + tid;
        int n = e >> 2, ku = e & 3;
        cpasync16(smem_base + SM_B + n*BROW + ku*16, &g_wbf_t[(size_t)n * Hh + ku*8]);
    }
    cp_commit();

    #pragma unroll 4
    for (int u = 0; u < 32; u++) {
        int e = u * 256 + tid;
        int row = e >> 7, c4 = e & 127;
        float4 v = *(const float4*)&Hd[(size_t)(m0 + row) * Hh + c4*4];
        __nv_bfloat162 lo = __floats2bfloat162_rn(v.x, v.y);
        __nv_bfloat162 hi = __floats2bfloat162_rn(v.z, v.w);
        uint32_t plo = *(uint32_t*)&lo, phi = *(uint32_t*)&hi;
        uint32_t off = (uint32_t)row*1024 + (((uint32_t)c4*8) ^ (((uint32_t)(row & 7)) << 4));
        asm volatile("st.shared.v2.b32 [%0], {%1, %2};"
                     :: "r"(smem_base + off), "r"(plo), "r"(phi) : "memory");
    }

    float acc[2][4][4];
    float psum[2][2] = {};
    int qr = lane >> 2, qc = (lane & 3) * 2;

    for (int nc = 0; nc < 4; nc++) {
        #pragma unroll
        for (int mt = 0; mt < 2; mt++)
            #pragma unroll
            for (int nt = 0; nt < 4; nt++)
                #pragma unroll
                for (int c = 0; c < 4; c++) acc[mt][nt][c] = 0.f;

        for (int kc = 0; kc < 16; kc++) {
            int g = nc * 16 + kc;
            cp_wait<0>();
            __syncthreads();
            int buf = g & 1;
            if (g < 63) {
                int g1 = g + 1, nc1 = g1 >> 4, kc1 = g1 & 15;
                uint32_t dstb = smem_base + SM_B + (buf ^ 1) * BSZ;
                #pragma unroll
                for (int u = 0; u < 2; u++) {
                    int e = u * 256 + tid;
                    int n = e >> 2, ku = e & 3;
                    cpasync16(dstb + n*BROW + ku*16,
                              &g_wbf_t[(size_t)(nc1*128 + n) * Hh + kc1*32 + ku*8]);
                }
                cp_commit();
            }
            uint32_t Bst = smem_base + SM_B + buf * BSZ;
            int kcb = kc * 64;
            #pragma unroll
            for (int ks = 0; ks < 2; ks++) {
                uint32_t a[2][4], bfr[2][4];
                uint32_t colA = (uint32_t)(kcb + ks*32 + ((lane >> 4) << 4));
                #pragma unroll
                for (int mt = 0; mt < 2; mt++) {
                    uint32_t row = (uint32_t)(wm*32 + mt*16 + (lane & 15));
                    ldsm_x4(a[mt], smem_base + row*1024 + (colA ^ ((row & 7) << 4)));
                }
                #pragma unroll
                for (int bp = 0; bp < 2; bp++) {
                    uint32_t row = (uint32_t)(wn*32 + bp*16 + ((lane >> 4) << 3) + (lane & 7));
                    uint32_t colb = (uint32_t)(ks*32 + ((lane >> 3) & 1) * 16);
                    ldsm_x4(bfr[bp], Bst + row*BROW + colb);
                }
                #pragma unroll
                for (int mt = 0; mt < 2; mt++)
                    #pragma unroll
                    for (int nt = 0; nt < 4; nt++)
                        mma16816(acc[mt][nt], a[mt], &bfr[nt >> 1][(nt & 1) * 2]);
            }
        }
        #pragma unroll
        for (int mt = 0; mt < 2; mt++) {
            #pragma unroll
            for (int nt = 0; nt < 4; nt++) {
                int n = nc*128 + wn*32 + nt*8 + qc;
                float pb0 = __ldg(&pb[n]), pb1 = __ldg(&pb[n+1]);
                float sw0 = __ldg(&sw[n]), sw1 = __ldg(&sw[n+1]);
                __half2 h0 = __floats2half2_rn(acc[mt][nt][0] + pb0, acc[mt][nt][1] + pb1);
                uint32_t t0 = tanh2(*(uint32_t*)&h0);
                __half2 r0 = *(__half2*)&t0;
                psum[mt][0] += __low2float(r0) * sw0 + __high2float(r0) * sw1;
                __half2 h1 = __floats2half2_rn(acc[mt][nt][2] + pb0, acc[mt][nt][3] + pb1);
                uint32_t t1 = tanh2(*(uint32_t*)&h1);
                __half2 r1 = *(__half2*)&t1;
                psum[mt][1] += __low2float(r1) * sw0 + __high2float(r1) * sw1;
            }
        }
    }
    #pragma unroll
    for (int mt = 0; mt < 2; mt++)
        #pragma unroll
        for (int j = 0; j < 2; j++) {
            psum[mt][j] += __shfl_xor_sync(0xffffffffu, psum[mt][j], 1);
            psum[mt][j] += __shfl_xor_sync(0xffffffffu, psum[mt][j], 2);
        }
    __syncthreads();
    float* red = (float*)smem_raw;
    if ((lane & 3) == 0) {
        #pragma unroll
        for (int mt = 0; mt < 2; mt++) {
            int m = wm*32 + mt*16 + qr;
            red[m*4 + wn]     = psum[mt][0];
            red[(m+8)*4 + wn] = psum[mt][1];
        }
    }
    __syncthreads();
    if (tid < GM) {
        float s = red[tid*4] + red[tid*4+1] + red[tid*4+2] + red[tid*4+3];
        int c = cnt[m0 + tid]; if (c < 0) c = 0;
        g_logits[m0 + tid] = sb[0] + log1pf((float)c) + s;
    }
}

// ---------------- fused channel-logits + softmax: one block per (b,c) ----------------
__global__ __launch_bounds__(256) void k_chsoftmax(const float* __restrict__ act,
                                                   float* __restrict__ wout) {
    __shared__ float v[Ll];
    __shared__ float red[256];
    int bc = blockIdx.x;
    int b = bc >> 6, c = bc & 63;
    int tid = threadIdx.x;
    const float* ab = act + (size_t)b * Ll * Cc + c;
    const float* lb = g_logits + b * Ll;

    float mx = NEGV;
    #pragma unroll 4
    for (int i = tid; i < Ll; i += 256) {
        float a  = __ldg(&ab[(size_t)i * Cc]);
        float lg = lb[i];
        float x  = (a > 0.f) ? (lg + log1pf(a)) : NEGV;
        v[i] = x;
        mx = fmaxf(mx, x);
    }
    red[tid] = mx; __syncthreads();
    for (int s = 128; s; s >>= 1) { if (tid < s) red[tid] = fmaxf(red[tid], red[tid+s]); __syncthreads(); }
    mx = red[0]; __syncthreads();
    float sum = 0.f;
    #pragma unroll 4
    for (int i = tid; i < Ll; i += 256) {
        float e = __expf(v[i] - mx);
        v[i] = e;
        sum += e;
    }
    red[tid] = sum; __syncthreads();
    for (int s = 128; s; s >>= 1) { if (tid < s) red[tid] += red[tid+s]; __syncthreads(); }
    sum = red[0];
    int any = mx > -1e8f;
    if (tid == 0) g_hasany[bc] = any;
    float inv = any ? (1.f / sum) : 0.f;
    float* w = wout + (size_t)bc * Ll;
    #pragma unroll 4
    for (int i = tid; i < Ll; i += 256) w[i] = v[i] * inv;
}

// ---------------- zero contexts (float4) ----------------
__global__ void k_zeroctx() {
    int i = blockIdx.x * 256 + threadIdx.x;
    float4 z = {0.f, 0.f, 0.f, 0.f};
    ((float4*)g_ctx)[i] = z;
}

// ---------------- contexts via tf32 (unchanged) ----------------
#define CTX_AP 36
#define CTX_BP 72
__global__ __launch_bounds__(256) void k_ctx_tf32(const float* __restrict__ Hd,
                                                  const float* __restrict__ wts) {
    __shared__ float As[2][64*CTX_AP];
    __shared__ float Bs[2][32*CTX_BP];
    int b  = blockIdx.z;
    int h0 = blockIdx.x * 64;
    int l0 = blockIdx.y * 1024;
    int tid = threadIdx.x, lane = tid & 31, wid = tid >> 5;
    int wm = wid >> 2, wn = wid & 3;
    int g = lane >> 2, tq = lane & 3;
    const float* wb = wts + (size_t)b * Cc * Ll;
    const float* hb = Hd  + (size_t)b * Ll * Hh;

    uint32_t sA0 = smem_u32(&As[0][0]), sA1 = smem_u32(&As[1][0]);
    uint32_t sB0 = smem_u32(&Bs[0][0]), sB1 = smem_u32(&Bs[1][0]);

    {
        #pragma unroll
        for (int u = 0; u < 2; u++) {
            int e = u*256 + tid;
            int c = e >> 3, kq = e & 7;
            cpasync16(sA0 + (c*CTX_AP + kq*4)*4, &wb[(size_t)c * Ll + l0 + kq*4]);
        }
        #pragma unroll
        for (int u = 0; u < 2; u++) {
            int e = u*256 + tid;
            int kk = e >> 4, nq = e & 15;
            cpasync16(sB0 + (kk*CTX_BP + nq*4)*4, &hb[(size_t)(l0 + kk) * Hh + h0 + nq*4]);
        }
        cp_commit();
    }

    float acc[2][2][4] = {};
    for (int s = 0; s < 32; s++) {
        cp_wait<0>();
        __syncthreads();
        int buf = s & 1;
        if (s < 31) {
            int k0 = l0 + (s + 1) * 32;
            uint32_t dA = (buf ? sA0 : sA1), dB = (buf ? sB0 : sB1);
            #pragma unroll
            for (int u = 0; u < 2; u++) {
                int e = u*256 + tid;
                int c = e >> 3, kq = e & 7;
                cpasync16(dA + (c*CTX_AP + kq*4)*4, &wb[(size_t)c * Ll + k0 + kq*4]);
            }
            #pragma unroll
            for (int u = 0; u < 2; u++) {
                int e = u*256 + tid;
                int kk = e >> 4, nq = e & 15;
                cpasync16(dB + (kk*CTX_BP + nq*4)*4, &hb[(size_t)(k0 + kk) * Hh + h0 + nq*4]);
            }
            cp_commit();
        }
        const float* Ab = As[buf];
        const float* Bbuf = Bs[buf];
        #pragma unroll
        for (int ks = 0; ks < 4; ks++) {
            int kb = ks * 8;
            uint32_t af[2][4], bf[2][2];
            #pragma unroll
            for (int mt = 0; mt < 2; mt++) {
                int m = wm*32 + mt*16;
                af[mt][0] = f2tf32(Ab[(m + g    )*CTX_AP + kb + tq    ]);
                af[mt][1] = f2tf32(Ab[(m + g + 8)*CTX_AP + kb + tq    ]);
                af[mt][2] = f2tf32(Ab[(m + g    )*CTX_AP + kb + tq + 4]);
                af[mt][3] = f2tf32(Ab[(m + g + 8)*CTX_AP + kb + tq + 4]);
            }
            #pragma unroll
            for (int nt = 0; nt < 2; nt++) {
                int n = wn*16 + nt*8;
                bf[nt][0] = f2tf32(Bbuf[(kb + tq    )*CTX_BP + n + g]);
                bf[nt][1] = f2tf32(Bbuf[(kb + tq + 4)*CTX_BP + n + g]);
            }
            #pragma unroll
            for (int mt = 0; mt < 2; mt++)
                #pragma unroll
                for (int nt = 0; nt < 2; nt++)
                    mma_tf32(acc[mt][nt], af[mt], bf[nt]);
        }
    }
    #pragma unroll
    for (int mt = 0; mt < 2; mt++)
        #pragma unroll
        for (int nt = 0; nt < 2; nt++) {
            int m = wm*32 + mt*16 + g;
            int n = h0 + wn*16 + nt*8 + tq*2;
            float* base0 = &g_ctx[((size_t)(b*Cc + m)) * Hh + n];
            atomicAdd(base0,     acc[mt][nt][0]);
            atomicAdd(base0 + 1, acc[mt][nt][1]);
            float* base1 = &g_ctx[((size_t)(b*Cc + m + 8)) * Hh + n];
            atomicAdd(base1,     acc[mt][nt][2]);
            atomicAdd(base1 + 1, acc[mt][nt][3]);
        }
}

// ---------------- final v4: tf32 MMA, ctxfix fused into ct load ----------------
#define FP 72
__global__ __launch_bounds__(256) void k_final4(const float* __restrict__ Hd,
                                                const float* __restrict__ act,
                                                const int* __restrict__ cnt,
                                                const int* __restrict__ msk,
                                                float* __restrict__ out) {
    __shared__ float s[64*FP];
    __shared__ float ct[64*FP];
    __shared__ float gate[64];
    __shared__ int   mk[64];
    __shared__ int   ha[64];
    int b  = blockIdx.y;
    int l0 = blockIdx.x * 64;
    int tid = threadIdx.x, lane = tid & 31, wid = tid >> 5;
    int wm = wid >> 2, wn = wid & 3;
    int g = lane >> 2, tq = lane & 3;

    #pragma unroll
    for (int u = 0; u < 4; u++) {
        int e = u * 256 + tid;
        int l = e >> 4, c4 = e & 15;
        float4 v = *(const float4*)&act[((size_t)(b*Ll + l0 + l)) * Cc + c4*4];
        s[l*FP + c4*4 + 0] = fmaxf(v.x, 0.f);
        s[l*FP + c4*4 + 1] = fmaxf(v.y, 0.f);
        s[l*FP + c4*4 + 2] = fmaxf(v.z, 0.f);
        s[l*FP + c4*4 + 3] = fmaxf(v.w, 0.f);
    }
    __syncthreads();
    if (tid < 64) {
        float sum = 0.f;
        #pragma unroll 8
        for (int c = 0; c < 64; c++) sum += s[tid*FP + c];
        float inv = 1.f / fmaxf(sum, 1.f);
        #pragma unroll 8
        for (int c = 0; c < 64; c++) s[tid*FP + c] *= inv;
        int gi = b*Ll + l0 + tid;
        gate[tid] = 1.f + (float)cnt[gi] / fmaxf((float)g_maxi[b], 1.f);
        mk[tid] = msk[gi];
        ha[tid] = g_hasany[b*Cc + tid];
    }
    __syncthreads();

    const float* lastrow = &Hd[((size_t)(b*Ll + Ll - 1)) * Hh];
    for (int h0 = 0; h0 < Hh; h0 += 64) {
        #pragma unroll
        for (int u = 0; u < 4; u++) {
            int e = u * 256 + tid;
            int c = e >> 4, h4 = e & 15;
            float4 v;
            if (ha[c]) v = *(const float4*)&g_ctx[((size_t)(b*Cc + c)) * Hh + h0 + h4*4];
            else       v = *(const float4*)&lastrow[h0 + h4*4];
            *(float4*)&ct[c*FP + h4*4] = v;
        }
        __syncthreads();
        float acc[2][2][4] = {};
        #pragma unroll
        for (int ks = 0; ks < 8; ks++) {
            int kb = ks * 8;
            uint32_t af[2][4], bf[2][2];
            #pragma unroll
            for (int mt = 0; mt < 2; mt++) {
                int m = wm*32 + mt*16;
                af[mt][0] = f2tf32(s[(m + g    )*FP + kb + tq    ]);
                af[mt][1] = f2tf32(s[(m + g + 8)*FP + kb + tq    ]);
                af[mt][2] = f2tf32(s[(m + g    )*FP + kb + tq + 4]);
                af[mt][3] = f2tf32(s[(m + g + 8)*FP + kb + tq + 4]);
            }
            #pragma unroll
            for (int nt = 0; nt < 2; nt++) {
                int n = wn*16 + nt*8;
                bf[nt][0] = f2tf32(ct[(kb + tq    )*FP + n + g]);
                bf[nt][1] = f2tf32(ct[(kb + tq + 4)*FP + n + g]);
            }
            #pragma unroll
            for (int mt = 0; mt < 2; mt++)
                #pragma unroll
                for (int nt = 0; nt < 2; nt++)
                    mma_tf32(acc[mt][nt], af[mt], bf[nt]);
        }
        #pragma unroll
        for (int mt = 0; mt < 2; mt++) {
            int l = wm*32 + mt*16 + g;
            int gi0 = b*Ll + l0 + l;
            float g0 = gate[l];     bool m0 = mk[l] != 0;
            float g1 = gate[l+8];   bool m1 = mk[l+8] != 0;
            #pragma unroll
            for (int nt = 0; nt < 2; nt++) {
                int n = h0 + wn*16 + nt*8 + tq*2;
                size_t o0 = (size_t)gi0 * Hh + n;
                out[o0]   = m0 ? acc[mt][nt][0] * g0 : Hd[o0];
                out[o0+1] = m0 ? acc[mt][nt][1] * g0 : Hd[o0+1];
                size_t o1 = (size_t)(gi0 + 8) * Hh + n;
                out[o1]   = m1 ? acc[mt][nt][2] * g1 : Hd[o1];
                out[o1+1] = m1 ? acc[mt][nt][3] * g1 : Hd[o1+1];
            }
        }
        __syncthreads();
    }
}

// ---------------- launch ----------------
extern "C" void kernel_launch(void* const* d_in, const int* in_sizes, int n_in,
                              void* d_out, int out_size) {
    const float* hidden = (const float*)d_in[0];
    const int*   mask   = (const int*)d_in[1];
    const int*   cnt    = (const int*)d_in[2];
    const float* act    = (const float*)d_in[3];
    const float* pw     = (const float*)d_in[4];
    const float* pb     = (const float*)d_in[5];
    const float* sw     = (const float*)d_in[6];
    const float* sb     = (const float*)d_in[7];
    float* out  = (float*)d_out;
    float* wout = out + OUT_ATT;

    static bool attr_done = false;
    if (!attr_done) {
        cudaFuncSetAttribute(k_gemm1_v4, cudaFuncAttributeMaxDynamicSharedMemorySize, GEMM_SMEM);
        attr_done = true;
    }

    k_cvt_wT<<<dim3(Aa/32, Aa/32), dim3(32,32)>>>(pw);
    k_maxcount<<<Bb*8, 512>>>(cnt);
    k_gemm1_v4<<<BL/GM, 256, GEMM_SMEM>>>(hidden, pb, sw, cnt, sb);
    k_chsoftmax<<<Bb*Cc, 256>>>(act, wout);
    k_zeroctx<<<Bb*Cc*Hh/4/256, 256>>>();
    k_ctx_tf32<<<dim3(Hh/64, Ll/1024, Bb), 256>>>(hidden, wout);
    k_final4<<<dim3(Ll/64, Bb), 256>>>(hidden, act, cnt, mask, out);
}

// round 11
// speedup vs baseline: 1.0466x; 1.0466x over previous
#include <cuda_runtime.h>
#include <cuda_bf16.h>
#include <cuda_fp16.h>
#include <cstdint>

#define Bb 8
#define Ll 4096
#define Hh 512
#define Cc 64
#define Aa 512
#define BL (Bb*Ll)
#define NEGV (-1000000000.0f)
#define OUT_ATT ((size_t)BL*Hh)

// ---- GEMM1 config: GM=64, A resident, triple-buffered B ----
#define GM 64
#define ABYTES (GM*1024)
#define BROW 80
#define BSZ (128*BROW)
#define SM_B ABYTES
#define GEMM_SMEM (ABYTES + 3*BSZ)   // 96256

// ---------------- scratch ----------------
__device__ float g_logits[BL];
__device__ float g_ctx[(size_t)Bb*Cc*Hh];
__device__ int   g_hasany[Bb*Cc];
__device__ int   g_maxi[Bb];
__device__ __nv_bfloat16 g_wbf_t[(size_t)Aa*Hh];

// ---------------- helpers ----------------
__device__ __forceinline__ uint32_t smem_u32(const void* p) {
    uint32_t a;
    asm("{ .reg .u64 t; cvta.to.shared.u64 t, %1; cvt.u32.u64 %0, t; }" : "=r"(a) : "l"(p));
    return a;
}
__device__ __forceinline__ void cpasync16(uint32_t dst, const void* src) {
    asm volatile("cp.async.cg.shared.global [%0], [%1], 16;" :: "r"(dst), "l"(src));
}
__device__ __forceinline__ void cp_commit() { asm volatile("cp.async.commit_group;"); }
template<int N> __device__ __forceinline__ void cp_wait() {
    asm volatile("cp.async.wait_group %0;" :: "n"(N));
}
__device__ __forceinline__ void ldsm_x4(uint32_t* r, uint32_t addr) {
    asm volatile("ldmatrix.sync.aligned.m8n8.x4.shared.b16 {%0,%1,%2,%3}, [%4];"
        : "=r"(r[0]), "=r"(r[1]), "=r"(r[2]), "=r"(r[3]) : "r"(addr));
}
__device__ __forceinline__ void mma16816(float* c, const uint32_t* a, const uint32_t* b) {
    asm volatile(
        "mma.sync.aligned.m16n8k16.row.col.f32.bf16.bf16.f32 "
        "{%0,%1,%2,%3}, {%4,%5,%6,%7}, {%8,%9}, {%0,%1,%2,%3};"
        : "+f"(c[0]), "+f"(c[1]), "+f"(c[2]), "+f"(c[3])
        : "r"(a[0]), "r"(a[1]), "r"(a[2]), "r"(a[3]), "r"(b[0]), "r"(b[1]));
}
__device__ __forceinline__ void mma_tf32(float* c, const uint32_t* a, const uint32_t* b) {
    asm volatile(
        "mma.sync.aligned.m16n8k8.row.col.f32.tf32.tf32.f32 "
        "{%0,%1,%2,%3}, {%4,%5,%6,%7}, {%8,%9}, {%0,%1,%2,%3};"
        : "+f"(c[0]), "+f"(c[1]), "+f"(c[2]), "+f"(c[3])
        : "r"(a[0]), "r"(a[1]), "r"(a[2]), "r"(a[3]), "r"(b[0]), "r"(b[1]));
}
__device__ __forceinline__ uint32_t f2tf32(float x) {
    uint32_t r;
    asm("cvt.rna.tf32.f32 %0, %1;" : "=r"(r) : "f"(x));
    return r;
}
__device__ __forceinline__ uint32_t tanh2(uint32_t x) {
    uint32_t r;
    asm("tanh.approx.f16x2 %0, %1;" : "=r"(r) : "r"(x));
    return r;
}

// ---------------- transpose + convert W ----------------
__global__ void k_cvt_wT(const float* __restrict__ W) {
    __shared__ float tile[32][33];
    int tx = threadIdx.x, ty = threadIdx.y;
    int k = blockIdx.x * 32 + ty;
    int n = blockIdx.y * 32 + tx;
    tile[ty][tx] = W[(size_t)k * Aa + n];
    __syncthreads();
    int no = blockIdx.y * 32 + ty;
    int ko = blockIdx.x * 32 + tx;
    g_wbf_t[(size_t)no * Hh + ko] = __float2bfloat16(tile[tx][ty]);
}

// ---------------- per-batch max count ----------------
__global__ void k_maxcount(const int* __restrict__ cnt) {
    int b = blockIdx.x >> 3, seg = blockIdx.x & 7;
    int v = cnt[b*Ll + seg*512 + threadIdx.x];
    #pragma unroll
    for (int o = 16; o; o >>= 1) v = max(v, __shfl_xor_sync(0xffffffffu, v, o));
    if ((threadIdx.x & 31) == 0) atomicMax(&g_maxi[b], v);
}

// ---------------- GEMM1 v5: triple-buffered B, 2-deep prefetch ----------------
extern __shared__ char smem_raw[];

__device__ __forceinline__ void g1_issue_chunk(uint32_t smem_base, int tid, int g) {
    int nc = g >> 4, kc = g & 15;
    uint32_t dstb = smem_base + SM_B + (g % 3) * BSZ;
    #pragma unroll
    for (int u = 0; u < 2; u++) {
        int e = u * 256 + tid;
        int n = e >> 2, ku = e & 3;
        cpasync16(dstb + n*BROW + ku*16,
                  &g_wbf_t[(size_t)(nc*128 + n) * Hh + kc*32 + ku*8]);
    }
    cp_commit();
}

__global__ __launch_bounds__(256)
void k_gemm1_v5(const float* __restrict__ Hd,
                const float* __restrict__ pb, const float* __restrict__ sw,
                const int* __restrict__ cnt, const float* __restrict__ sb) {
    uint32_t smem_base = smem_u32(smem_raw);
    int tid = threadIdx.x, lane = tid & 31, wid = tid >> 5;
    int wm = wid >> 2, wn = wid & 3;
    int m0 = blockIdx.x * GM;

    g1_issue_chunk(smem_base, tid, 0);
    g1_issue_chunk(smem_base, tid, 1);

    // A resident: 64x512 f32 -> bf16
    #pragma unroll 4
    for (int u = 0; u < 32; u++) {
        int e = u * 256 + tid;
        int row = e >> 7, c4 = e & 127;
        float4 v = *(const float4*)&Hd[(size_t)(m0 + row) * Hh + c4*4];
        __nv_bfloat162 lo = __floats2bfloat162_rn(v.x, v.y);
        __nv_bfloat162 hi = __floats2bfloat162_rn(v.z, v.w);
        uint32_t plo = *(uint32_t*)&lo, phi = *(uint32_t*)&hi;
        uint32_t off = (uint32_t)row*1024 + (((uint32_t)c4*8) ^ (((uint32_t)(row & 7)) << 4));
        asm volatile("st.shared.v2.b32 [%0], {%1, %2};"
                     :: "r"(smem_base + off), "r"(plo), "r"(phi) : "memory");
    }

    float acc[2][4][4];
    float psum[2][2] = {};
    int qr = lane >> 2, qc = (lane & 3) * 2;

    for (int nc = 0; nc < 4; nc++) {
        #pragma unroll
        for (int mt = 0; mt < 2; mt++)
            #pragma unroll
            for (int nt = 0; nt < 4; nt++)
                #pragma unroll
                for (int c = 0; c < 4; c++) acc[mt][nt][c] = 0.f;

        for (int kc = 0; kc < 16; kc++) {
            int g = nc * 16 + kc;
            if (g == 63) cp_wait<0>(); else cp_wait<1>();
            __syncthreads();
            if (g + 2 < 64) g1_issue_chunk(smem_base, tid, g + 2);
            uint32_t Bst = smem_base + SM_B + (g % 3) * BSZ;
            int kcb = kc * 64;
            #pragma unroll
            for (int ks = 0; ks < 2; ks++) {
                uint32_t a[2][4], bfr[2][4];
                uint32_t colA = (uint32_t)(kcb + ks*32 + ((lane >> 4) << 4));
                #pragma unroll
                for (int mt = 0; mt < 2; mt++) {
                    uint32_t row = (uint32_t)(wm*32 + mt*16 + (lane & 15));
                    ldsm_x4(a[mt], smem_base + row*1024 + (colA ^ ((row & 7) << 4)));
                }
                #pragma unroll
                for (int bp = 0; bp < 2; bp++) {
                    uint32_t row = (uint32_t)(wn*32 + bp*16 + ((lane >> 4) << 3) + (lane & 7));
                    uint32_t colb = (uint32_t)(ks*32 + ((lane >> 3) & 1) * 16);
                    ldsm_x4(bfr[bp], Bst + row*BROW + colb);
                }
                #pragma unroll
                for (int mt = 0; mt < 2; mt++)
                    #pragma unroll
                    for (int nt = 0; nt < 4; nt++)
                        mma16816(acc[mt][nt], a[mt], &bfr[nt >> 1][(nt & 1) * 2]);
            }
        }
        #pragma unroll
        for (int mt = 0; mt < 2; mt++) {
            #pragma unroll
            for (int nt = 0; nt < 4; nt++) {
                int n = nc*128 + wn*32 + nt*8 + qc;
                float pb0 = __ldg(&pb[n]), pb1 = __ldg(&pb[n+1]);
                float sw0 = __ldg(&sw[n]), sw1 = __ldg(&sw[n+1]);
                __half2 h0 = __floats2half2_rn(acc[mt][nt][0] + pb0, acc[mt][nt][1] + pb1);
                uint32_t t0 = tanh2(*(uint32_t*)&h0);
                __half2 r0 = *(__half2*)&t0;
                psum[mt][0] += __low2float(r0) * sw0 + __high2float(r0) * sw1;
                __half2 h1 = __floats2half2_rn(acc[mt][nt][2] + pb0, acc[mt][nt][3] + pb1);
                uint32_t t1 = tanh2(*(uint32_t*)&h1);
                __half2 r1 = *(__half2*)&t1;
                psum[mt][1] += __low2float(r1) * sw0 + __high2float(r1) * sw1;
            }
        }
    }
    #pragma unroll
    for (int mt = 0; mt < 2; mt++)
        #pragma unroll
        for (int j = 0; j < 2; j++) {
            psum[mt][j] += __shfl_xor_sync(0xffffffffu, psum[mt][j], 1);
            psum[mt][j] += __shfl_xor_sync(0xffffffffu, psum[mt][j], 2);
        }
    __syncthreads();
    float* red = (float*)smem_raw;
    if ((lane & 3) == 0) {
        #pragma unroll
        for (int mt = 0; mt < 2; mt++) {
            int m = wm*32 + mt*16 + qr;
            red[m*4 + wn]     = psum[mt][0];
            red[(m+8)*4 + wn] = psum[mt][1];
        }
    }
    __syncthreads();
    if (tid < GM) {
        float s = red[tid*4] + red[tid*4+1] + red[tid*4+2] + red[tid*4+3];
        int c = cnt[m0 + tid]; if (c < 0) c = 0;
        g_logits[m0 + tid] = sb[0] + log1pf((float)c) + s;
    }
}

// ---------------- fused channel-logits + softmax ----------------
__global__ __launch_bounds__(256) void k_chsoftmax(const float* __restrict__ act,
                                                   float* __restrict__ wout) {
    __shared__ float v[Ll];
    __shared__ float red[256];
    int bc = blockIdx.x;
    int b = bc >> 6, c = bc & 63;
    int tid = threadIdx.x;
    const float* ab = act + (size_t)b * Ll * Cc + c;
    const float* lb = g_logits + b * Ll;

    float mx = NEGV;
    #pragma unroll 4
    for (int i = tid; i < Ll; i += 256) {
        float a  = __ldg(&ab[(size_t)i * Cc]);
        float lg = lb[i];
        float x  = (a > 0.f) ? (lg + log1pf(a)) : NEGV;
        v[i] = x;
        mx = fmaxf(mx, x);
    }
    red[tid] = mx; __syncthreads();
    for (int s = 128; s; s >>= 1) { if (tid < s) red[tid] = fmaxf(red[tid], red[tid+s]); __syncthreads(); }
    mx = red[0]; __syncthreads();
    float sum = 0.f;
    #pragma unroll 4
    for (int i = tid; i < Ll; i += 256) {
        float e = __expf(v[i] - mx);
        v[i] = e;
        sum += e;
    }
    red[tid] = sum; __syncthreads();
    for (int s = 128; s; s >>= 1) { if (tid < s) red[tid] += red[tid+s]; __syncthreads(); }
    sum = red[0];
    int any = mx > -1e8f;
    if (tid == 0) g_hasany[bc] = any;
    float inv = any ? (1.f / sum) : 0.f;
    float* w = wout + (size_t)bc * Ll;
    #pragma unroll 4
    for (int i = tid; i < Ll; i += 256) w[i] = v[i] * inv;
}

// ---------------- zero contexts ----------------
__global__ void k_zeroctx() {
    int i = blockIdx.x * 256 + threadIdx.x;
    float4 z = {0.f, 0.f, 0.f, 0.f};
    ((float4*)g_ctx)[i] = z;
}

// ---------------- contexts tf32 v2: 3-stage pipeline, L split 8 ----------------
#define CTX_AP 36
#define CTX_BP 72
#define CTX_KLEN 512
#define CTX_NST (CTX_KLEN/32)   // 16

__device__ __forceinline__ void ctx_issue(uint32_t sA, uint32_t sB,
                                          const float* wb, const float* hb,
                                          int tid, int k0, int h0) {
    #pragma unroll
    for (int u = 0; u < 2; u++) {
        int e = u*256 + tid;
        int c = e >> 3, kq = e & 7;
        cpasync16(sA + (c*CTX_AP + kq*4)*4, &wb[(size_t)c * Ll + k0 + kq*4]);
    }
    #pragma unroll
    for (int u = 0; u < 2; u++) {
        int e = u*256 + tid;
        int kk = e >> 4, nq = e & 15;
        cpasync16(sB + (kk*CTX_BP + nq*4)*4, &hb[(size_t)(k0 + kk) * Hh + h0 + nq*4]);
    }
    cp_commit();
}

__global__ __launch_bounds__(256) void k_ctx_tf32(const float* __restrict__ Hd,
                                                  const float* __restrict__ wts) {
    __shared__ float As[3][64*CTX_AP];
    __shared__ float Bs[3][32*CTX_BP];
    int b  = blockIdx.z;
    int h0 = blockIdx.x * 64;
    int l0 = blockIdx.y * CTX_KLEN;
    int tid = threadIdx.x, lane = tid & 31, wid = tid >> 5;
    int wm = wid >> 2, wn = wid & 3;
    int g = lane >> 2, tq = lane & 3;
    const float* wb = wts + (size_t)b * Cc * Ll;
    const float* hb = Hd  + (size_t)b * Ll * Hh;

    uint32_t sA[3] = { smem_u32(&As[0][0]), smem_u32(&As[1][0]), smem_u32(&As[2][0]) };
    uint32_t sB[3] = { smem_u32(&Bs[0][0]), smem_u32(&Bs[1][0]), smem_u32(&Bs[2][0]) };

    ctx_issue(sA[0], sB[0], wb, hb, tid, l0, h0);
    ctx_issue(sA[1], sB[1], wb, hb, tid, l0 + 32, h0);

    float acc[2][2][4] = {};
    for (int s = 0; s < CTX_NST; s++) {
        if (s == CTX_NST-1) cp_wait<0>(); else cp_wait<1>();
        __syncthreads();
        if (s + 2 < CTX_NST)
            ctx_issue(sA[(s+2)%3], sB[(s+2)%3], wb, hb, tid, l0 + (s+2)*32, h0);
        const float* Ab = As[s%3];
        const float* Bbuf = Bs[s%3];
        #pragma unroll
        for (int ks = 0; ks < 4; ks++) {
            int kb = ks * 8;
            uint32_t af[2][4], bf[2][2];
            #pragma unroll
            for (int mt = 0; mt < 2; mt++) {
                int m = wm*32 + mt*16;
                af[mt][0] = f2tf32(Ab[(m + g    )*CTX_AP + kb + tq    ]);
                af[mt][1] = f2tf32(Ab[(m + g + 8)*CTX_AP + kb + tq    ]);
                af[mt][2] = f2tf32(Ab[(m + g    )*CTX_AP + kb + tq + 4]);
                af[mt][3] = f2tf32(Ab[(m + g + 8)*CTX_AP + kb + tq + 4]);
            }
            #pragma unroll
            for (int nt = 0; nt < 2; nt++) {
                int n = wn*16 + nt*8;
                bf[nt][0] = f2tf32(Bbuf[(kb + tq    )*CTX_BP + n + g]);
                bf[nt][1] = f2tf32(Bbuf[(kb + tq + 4)*CTX_BP + n + g]);
            }
            #pragma unroll
            for (int mt = 0; mt < 2; mt++)
                #pragma unroll
                for (int nt = 0; nt < 2; nt++)
                    mma_tf32(acc[mt][nt], af[mt], bf[nt]);
        }
    }
    #pragma unroll
    for (int mt = 0; mt < 2; mt++)
        #pragma unroll
        for (int nt = 0; nt < 2; nt++) {
            int m = wm*32 + mt*16 + g;
            int n = h0 + wn*16 + nt*8 + tq*2;
            float* base0 = &g_ctx[((size_t)(b*Cc + m)) * Hh + n];
            atomicAdd(base0,     acc[mt][nt][0]);
            atomicAdd(base0 + 1, acc[mt][nt][1]);
            float* base1 = &g_ctx[((size_t)(b*Cc + m + 8)) * Hh + n];
            atomicAdd(base1,     acc[mt][nt][2]);
            atomicAdd(base1 + 1, acc[mt][nt][3]);
        }
}

// ---------------- final v4: tf32 MMA, fused ctxfix (unchanged) ----------------
#define FP 72
__global__ __launch_bounds__(256) void k_final4(const float* __restrict__ Hd,
                                                const float* __restrict__ act,
                                                const int* __restrict__ cnt,
                                                const int* __restrict__ msk,
                                                float* __restrict__ out) {
    __shared__ float s[64*FP];
    __shared__ float ct[64*FP];
    __shared__ float gate[64];
    __shared__ int   mk[64];
    __shared__ int   ha[64];
    int b  = blockIdx.y;
    int l0 = blockIdx.x * 64;
    int tid = threadIdx.x, lane = tid & 31, wid = tid >> 5;
    int wm = wid >> 2, wn = wid & 3;
    int g = lane >> 2, tq = lane & 3;

    #pragma unroll
    for (int u = 0; u < 4; u++) {
        int e = u * 256 + tid;
        int l = e >> 4, c4 = e & 15;
        float4 v = *(const float4*)&act[((size_t)(b*Ll + l0 + l)) * Cc + c4*4];
        s[l*FP + c4*4 + 0] = fmaxf(v.x, 0.f);
        s[l*FP + c4*4 + 1] = fmaxf(v.y, 0.f);
        s[l*FP + c4*4 + 2] = fmaxf(v.z, 0.f);
        s[l*FP + c4*4 + 3] = fmaxf(v.w, 0.f);
    }
    __syncthreads();
    if (tid < 64) {
        float sum = 0.f;
        #pragma unroll 8
        for (int c = 0; c < 64; c++) sum += s[tid*FP + c];
        float inv = 1.f / fmaxf(sum, 1.f);
        #pragma unroll 8
        for (int c = 0; c < 64; c++) s[tid*FP + c] *= inv;
        int gi = b*Ll + l0 + tid;
        gate[tid] = 1.f + (float)cnt[gi] / fmaxf((float)g_maxi[b], 1.f);
        mk[tid] = msk[gi];
        ha[tid] = g_hasany[b*Cc + tid];
    }
    __syncthreads();

    const float* lastrow = &Hd[((size_t)(b*Ll + Ll - 1)) * Hh];
    for (int h0 = 0; h0 < Hh; h0 += 64) {
        #pragma unroll
        for (int u = 0; u < 4; u++) {
            int e = u * 256 + tid;
            int c = e >> 4, h4 = e & 15;
            float4 v;
            if (ha[c]) v = *(const float4*)&g_ctx[((size_t)(b*Cc + c)) * Hh + h0 + h4*4];
            else       v = *(const float4*)&lastrow[h0 + h4*4];
            *(float4*)&ct[c*FP + h4*4] = v;
        }
        __syncthreads();
        float acc[2][2][4] = {};
        #pragma unroll
        for (int ks = 0; ks < 8; ks++) {
            int kb = ks * 8;
            uint32_t af[2][4], bf[2][2];
            #pragma unroll
            for (int mt = 0; mt < 2; mt++) {
                int m = wm*32 + mt*16;
                af[mt][0] = f2tf32(s[(m + g    )*FP + kb + tq    ]);
                af[mt][1] = f2tf32(s[(m + g + 8)*FP + kb + tq    ]);
                af[mt][2] = f2tf32(s[(m + g    )*FP + kb + tq + 4]);
                af[mt][3] = f2tf32(s[(m + g + 8)*FP + kb + tq + 4]);
            }
            #pragma unroll
            for (int nt = 0; nt < 2; nt++) {
                int n = wn*16 + nt*8;
                bf[nt][0] = f2tf32(ct[(kb + tq    )*FP + n + g]);
                bf[nt][1] = f2tf32(ct[(kb + tq + 4)*FP + n + g]);
            }
            #pragma unroll
            for (int mt = 0; mt < 2; mt++)
                #pragma unroll
                for (int nt = 0; nt < 2; nt++)
                    mma_tf32(acc[mt][nt], af[mt], bf[nt]);
        }
        #pragma unroll
        for (int mt = 0; mt < 2; mt++) {
            int l = wm*32 + mt*16 + g;
            int gi0 = b*Ll + l0 + l;
            float g0 = gate[l];     bool m0 = mk[l] != 0;
            float g1 = gate[l+8];   bool m1 = mk[l+8] != 0;
            #pragma unroll
            for (int nt = 0; nt < 2; nt++) {
                int n = h0 + wn*16 + nt*8 + tq*2;
                size_t o0 = (size_t)gi0 * Hh + n;
                out[o0]   = m0 ? acc[mt][nt][0] * g0 : Hd[o0];
                out[o0+1] = m0 ? acc[mt][nt][1] * g0 : Hd[o0+1];
                size_t o1 = (size_t)(gi0 + 8) * Hh + n;
                out[o1]   = m1 ? acc[mt][nt][2] * g1 : Hd[o1];
                out[o1+1] = m1 ? acc[mt][nt][3] * g1 : Hd[o1+1];
            }
        }
        __syncthreads();
    }
}

// ---------------- launch ----------------
extern "C" void kernel_launch(void* const* d_in, const int* in_sizes, int n_in,
                              void* d_out, int out_size) {
    const float* hidden = (const float*)d_in[0];
    const int*   mask   = (const int*)d_in[1];
    const int*   cnt    = (const int*)d_in[2];
    const float* act    = (const float*)d_in[3];
    const float* pw     = (const float*)d_in[4];
    const float* pb     = (const float*)d_in[5];
    const float* sw     = (const float*)d_in[6];
    const float* sb     = (const float*)d_in[7];
    float* out  = (float*)d_out;
    float* wout = out + OUT_ATT;

    static bool attr_done = false;
    if (!attr_done) {
        cudaFuncSetAttribute(k_gemm1_v5, cudaFuncAttributeMaxDynamicSharedMemorySize, GEMM_SMEM);
        attr_done = true;
    }

    k_cvt_wT<<<dim3(Aa/32, Aa/32), dim3(32,32)>>>(pw);
    k_maxcount<<<Bb*8, 512>>>(cnt);
    k_gemm1_v5<<<BL/GM, 256, GEMM_SMEM>>>(hidden, pb, sw, cnt, sb);
    k_chsoftmax<<<Bb*Cc, 256>>>(act, wout);
    k_zeroctx<<<Bb*Cc*Hh/4/256, 256>>>();
    k_ctx_tf32<<<dim3(Hh/64, Ll/CTX_KLEN, Bb), 256>>>(hidden, wout);
    k_final4<<<dim3(Ll/64, Bb), 256>>>(hidden, act, cnt, mask, out);
}